// round 10
// baseline (speedup 1.0000x reference)
#include <cuda_runtime.h>
#include <cstdint>

typedef unsigned long long ull;

#define NCTA      4
#define HID       128
#define NTHREADS  512
#define NWIN      252
#define TT        256
#define PADK      132     // weight row stride (floats): conflict-free 4-phase
#define HCH       20      // h: 20 floats per 16-float chunk (bank spread)
#define HB        160     // per-batch h stride = 8 * HCH

struct Smem {
    float W1s[128 * PADK];   // Wih1, row lr = gi*64 + u*2 + gh  (gate g = 2*gi+gh)
    float U1s[128 * PADK];   // Whh1
    float U0s[128 * PADK];   // Whh0
    float W0s[128 * 4];      // Wih0 (3 cols + pad)
    float b0s[128];
    float b1s[128];
    float h0buf[2][4 * HB];  // ping-pong, cluster-shared
    float h1buf[2][4 * HB];
    float xin[4 * 4 * 4];    // [t][b][f pad4]
    float Wl[2 * HID];
    float winbuf[4 * 4 * 2];
    float pred[4 * 2];
    float bl[2];
};

#define FFMA2(acc, w, h) \
    asm("fma.rn.f32x2 %0, %1, %2, %0;" : "+l"(acc) : "l"(w), "l"(h))

__device__ __forceinline__ float hsum2(ull a) {
    float lo, hi;
    asm("mov.b64 {%0, %1}, %2;" : "=f"(lo), "=f"(hi) : "l"(a));
    return lo + hi;
}

__device__ __forceinline__ void cluster_sync_all() {
    asm volatile("barrier.cluster.arrive.aligned;" ::: "memory");
    asm volatile("barrier.cluster.wait.aligned;" ::: "memory");
}

__device__ __forceinline__ float sigf(float x) {
    return 1.0f / (1.0f + __expf(-x));
}

__device__ __forceinline__ int hidx(int j) { return (j >> 4) * HCH + (j & 15); }

// broadcast one float to the same smem slot in all 4 cluster CTAs
__device__ __forceinline__ void push4(float v, float* dst) {
    uint32_t la = (uint32_t)__cvta_generic_to_shared(dst);
#pragma unroll
    for (int rr = 0; rr < NCTA; rr++) {
        uint32_t ra;
        asm volatile("mapa.shared::cluster.u32 %0, %1, %2;"
                     : "=r"(ra) : "r"(la), "r"(rr));
        asm volatile("st.shared::cluster.f32 [%0], %1;"
                     :: "r"(ra), "f"(v) : "memory");
    }
}

__device__ __forceinline__ float act2(float g0, float g1, float g2, float g3,
                                      float& c, bool first) {
    float ii = sigf(g0), ff = sigf(g1), tg = tanhf(g2), oo = sigf(g3);
    float cc = first ? ii * tg : fmaf(ff, c, ii * tg);
    c = cc;
    return oo * tanhf(cc);
}

// One fused stage:  gates1 = Wih1·h0 (+ Whh1·h1 if HH1) + b1
//                   gates0 = Whh0·h0 + Wih0·x[t_next] + b0     (if G0)
// followed by in-warp kq-reduction, gh gate-exchange, activation, DSMEM push.
template<bool HH1, bool G0, bool FIRST1>
__device__ __forceinline__ void stage(Smem& s, int pw, int u, int gh, int kq,
                                      int lrA, int lrB, int t_next, int rank,
                                      float* c0, float* c1,
                                      float* h0last, float* h1last) {
    const float* h0r = s.h0buf[pw];
    const float* h1r = s.h1buf[pw];
    ull A1[2][4] = {};
    ull A0[2][4] = {};
    const int kb = kq * HCH;
    const float* wA1 = &s.W1s[lrA * PADK + kq * 16];
    const float* wB1 = &s.W1s[lrB * PADK + kq * 16];
    const float* uA1 = &s.U1s[lrA * PADK + kq * 16];
    const float* uB1 = &s.U1s[lrB * PADK + kq * 16];
    const float* uA0 = &s.U0s[lrA * PADK + kq * 16];
    const float* uB0 = &s.U0s[lrB * PADK + kq * 16];
#pragma unroll
    for (int k4 = 0; k4 < 4; k4++) {
        ulonglong2 w1a = *(const ulonglong2*)(wA1 + k4 * 4);
        ulonglong2 w1b = *(const ulonglong2*)(wB1 + k4 * 4);
        ulonglong2 u1a = {0, 0}, u1b = {0, 0}, u0a = {0, 0}, u0b = {0, 0};
        if (HH1) {
            u1a = *(const ulonglong2*)(uA1 + k4 * 4);
            u1b = *(const ulonglong2*)(uB1 + k4 * 4);
        }
        if (G0) {
            u0a = *(const ulonglong2*)(uA0 + k4 * 4);
            u0b = *(const ulonglong2*)(uB0 + k4 * 4);
        }
#pragma unroll
        for (int b = 0; b < 4; b++) {
            ulonglong2 h0v = *(const ulonglong2*)&h0r[b * HB + kb + k4 * 4];
            FFMA2(A1[0][b], w1a.x, h0v.x); FFMA2(A1[0][b], w1a.y, h0v.y);
            FFMA2(A1[1][b], w1b.x, h0v.x); FFMA2(A1[1][b], w1b.y, h0v.y);
            if (G0) {
                FFMA2(A0[0][b], u0a.x, h0v.x); FFMA2(A0[0][b], u0a.y, h0v.y);
                FFMA2(A0[1][b], u0b.x, h0v.x); FFMA2(A0[1][b], u0b.y, h0v.y);
            }
            if (HH1) {
                ulonglong2 h1v = *(const ulonglong2*)&h1r[b * HB + kb + k4 * 4];
                FFMA2(A1[0][b], u1a.x, h1v.x); FFMA2(A1[0][b], u1a.y, h1v.y);
                FFMA2(A1[1][b], u1b.x, h1v.x); FFMA2(A1[1][b], u1b.y, h1v.y);
            }
        }
    }
    float s1v[2][4], s0v[2][4];
#pragma unroll
    for (int gi = 0; gi < 2; gi++)
#pragma unroll
        for (int b = 0; b < 4; b++) {
            s1v[gi][b] = hsum2(A1[gi][b]);
            if (G0) s0v[gi][b] = hsum2(A0[gi][b]);
        }
    // reduce over kq (lane bits 0..2) — no barrier needed
#pragma unroll
    for (int d = 1; d <= 4; d <<= 1) {
#pragma unroll
        for (int gi = 0; gi < 2; gi++)
#pragma unroll
            for (int b = 0; b < 4; b++) {
                s1v[gi][b] += __shfl_xor_sync(0xFFFFFFFFu, s1v[gi][b], d);
                if (G0) s0v[gi][b] += __shfl_xor_sync(0xFFFFFFFFu, s0v[gi][b], d);
            }
    }
    // bias (+ Wih0·x for L0)
#pragma unroll
    for (int gi = 0; gi < 2; gi++) {
        int lr = gi ? lrB : lrA;
        float bb1 = s.b1s[lr];
#pragma unroll
        for (int b = 0; b < 4; b++) {
            s1v[gi][b] += bb1;
            if (G0) {
                const float* x = &s.xin[(t_next * 4 + b) * 4];
                const float* wv = &s.W0s[lr * 4];
                s0v[gi][b] += s.b0s[lr] + wv[0] * x[0] + wv[1] * x[1] + wv[2] * x[2];
            }
        }
    }
    // exchange gate-halves across gh (lane distance 8)
    int oh2 = 2 * (gh ^ 1);
    float r1[2][2], r0[2][2];
#pragma unroll
    for (int gi = 0; gi < 2; gi++)
#pragma unroll
        for (int j = 0; j < 2; j++) {
            r1[gi][j] = __shfl_xor_sync(0xFFFFFFFFu, s1v[gi][oh2 + j], 8);
            if (G0) r0[gi][j] = __shfl_xor_sync(0xFFFFFFFFu, s0v[gi][oh2 + j], 8);
        }
    if (kq == 0) {
        int jg = rank * 32 + u;
        int hix = hidx(jg);
#pragma unroll
        for (int j = 0; j < 2; j++) {
            int b = 2 * gh + j;
            float g0v = gh ? r1[0][j] : s1v[0][b];
            float g1v = gh ? s1v[0][b] : r1[0][j];
            float g2v = gh ? r1[1][j] : s1v[1][b];
            float g3v = gh ? s1v[1][b] : r1[1][j];
            float hh = act2(g0v, g1v, g2v, g3v, c1[j], FIRST1);
            h1last[j] = hh;
            push4(hh, &s.h1buf[pw ^ 1][b * HB + hix]);
            if (G0) {
                float a0 = gh ? r0[0][j] : s0v[0][b];
                float a1 = gh ? s0v[0][b] : r0[0][j];
                float a2 = gh ? r0[1][j] : s0v[1][b];
                float a3 = gh ? s0v[1][b] : r0[1][j];
                float h0 = act2(a0, a1, a2, a3, c0[j], false);
                h0last[j] = h0;
                push4(h0, &s.h0buf[pw ^ 1][b * HB + hix]);
            }
        }
    }
}

extern __shared__ float smem_raw[];

__global__ void __cluster_dims__(NCTA, 1, 1) __launch_bounds__(NTHREADS, 1)
lstm_kernel(const float* __restrict__ traj,
            const float* __restrict__ Wih0, const float* __restrict__ Whh0,
            const float* __restrict__ bih0, const float* __restrict__ bhh0,
            const float* __restrict__ Wih1, const float* __restrict__ Whh1,
            const float* __restrict__ bih1, const float* __restrict__ bhh1,
            const float* __restrict__ Wl,   const float* __restrict__ bl,
            float* __restrict__ out) {
    Smem& s = *reinterpret_cast<Smem*>(smem_raw);
    const int tid = threadIdx.x;
    uint32_t rank;
    asm("mov.u32 %0, %%cluster_ctarank;" : "=r"(rank));
    const int cluster = blockIdx.x / NCTA;
    const int gb0 = cluster * 4;

    // ---- weights: local row lr = gi*64 + u*2 + gh  <->  gate g = 2*gi+gh,
    //      global row gr = g*128 + rank*32 + u
    for (int i = tid; i < 128 * HID; i += NTHREADS) {
        int lr = i / HID, k = i % HID;
        int gi = lr >> 6, rem = lr & 63, uu = rem >> 1, ghb = rem & 1;
        int gr = (2 * gi + ghb) * 128 + (int)rank * 32 + uu;
        s.W1s[lr * PADK + k] = Wih1[gr * HID + k];
        s.U1s[lr * PADK + k] = Whh1[gr * HID + k];
        s.U0s[lr * PADK + k] = Whh0[gr * HID + k];
    }
    for (int lr = tid; lr < 128; lr += NTHREADS) {
        int gi = lr >> 6, rem = lr & 63, uu = rem >> 1, ghb = rem & 1;
        int gr = (2 * gi + ghb) * 128 + (int)rank * 32 + uu;
        s.W0s[lr * 4 + 0] = Wih0[gr * 3 + 0];
        s.W0s[lr * 4 + 1] = Wih0[gr * 3 + 1];
        s.W0s[lr * 4 + 2] = Wih0[gr * 3 + 2];
        s.W0s[lr * 4 + 3] = 0.0f;
        s.b0s[lr] = bih0[gr] + bhh0[gr];
        s.b1s[lr] = bih1[gr] + bhh1[gr];
    }
    for (int i = tid; i < 2 * HID; i += NTHREADS) s.Wl[i] = Wl[i];
    if (tid < 2) s.bl[tid] = bl[tid];
    __syncthreads();
    cluster_sync_all();

    const int u  = tid >> 4;
    const int gh = (tid >> 3) & 1;
    const int kq = tid & 7;
    const int lrA = u * 2 + gh;
    const int lrB = 64 + u * 2 + gh;

    int pw = 0;
    float c0[2] = {0.f, 0.f}, c1[2] = {0.f, 0.f};
    float h0last[2] = {0.f, 0.f}, h1last[2] = {0.f, 0.f};

    for (int w = 0; w < NWIN; w++) {
        // ---- build window inputs xin[t][b][f]
        if (tid < 64) {
            int t = tid >> 4, b = (tid >> 2) & 3, f = tid & 3;
            if (f < 3) {
                int gb = gb0 + b;
                float v;
                if (w == 0) {
                    v = traj[(gb * TT + t) * 3 + f];
                } else if (w < 4) {
                    if (t < 3) v = traj[(gb * TT + (w + t)) * 3 + f];
                    else v = (f == 0) ? traj[(gb * TT + (4 + w)) * 3 + 0]
                                      : s.winbuf[(b * 4 + 3) * 2 + (f - 1)];
                } else {
                    v = (f < 2) ? s.winbuf[(b * 4 + t) * 2 + f]
                                : traj[(gb * TT + (w + t)) * 3 + 0];
                }
                s.xin[(t * 4 + b) * 4 + f] = v;
            }
        }
        __syncthreads();

        // ---- s0: layer-0 @ t=0 (x only), computed directly by acting lanes
        if (kq == 0) {
            int jg = (int)rank * 32 + u;
            int hix = hidx(jg);
#pragma unroll
            for (int j = 0; j < 2; j++) {
                int b = 2 * gh + j;
                const float* x = &s.xin[(0 * 4 + b) * 4];
                float g4[4];
#pragma unroll
                for (int g = 0; g < 4; g++) {
                    int lr = (g >> 1) * 64 + u * 2 + (g & 1);
                    const float* wv = &s.W0s[lr * 4];
                    g4[g] = s.b0s[lr] + wv[0] * x[0] + wv[1] * x[1] + wv[2] * x[2];
                }
                float h0 = act2(g4[0], g4[1], g4[2], g4[3], c0[j], true);
                h0last[j] = h0;
                push4(h0, &s.h0buf[pw ^ 1][b * HB + hix]);
            }
        }
        cluster_sync_all();
        pw ^= 1;

        // ---- s1..s3: fused L1[t] + L0[t+1];  s4: L1[3] only
        stage<false, true, true >(s, pw, u, gh, kq, lrA, lrB, 1, (int)rank, c0, c1, h0last, h1last);
        cluster_sync_all(); pw ^= 1;
        stage<true,  true, false>(s, pw, u, gh, kq, lrA, lrB, 2, (int)rank, c0, c1, h0last, h1last);
        cluster_sync_all(); pw ^= 1;
        stage<true,  true, false>(s, pw, u, gh, kq, lrA, lrB, 3, (int)rank, c0, c1, h0last, h1last);
        cluster_sync_all(); pw ^= 1;
        stage<true,  false, false>(s, pw, u, gh, kq, lrA, lrB, 0, (int)rank, c0, c1, h0last, h1last);
        cluster_sync_all(); pw ^= 1;

        // ---- head: pred[b][o] = Wl[o,:]·h1[b,:] + bl[o]
        if (tid < 256) {
            int wid = tid >> 5, lane = tid & 31;
            int b = wid >> 1, o = wid & 1;
            const float4* wl4 = (const float4*)&s.Wl[o * HID];
            float4 a = wl4[lane];
            const float* hb = &s.h1buf[pw][b * HB + (lane >> 2) * HCH + (lane & 3) * 4];
            float4 hh = *(const float4*)hb;
            float p = a.x * hh.x + a.y * hh.y + a.z * hh.z + a.w * hh.w;
            p += __shfl_xor_sync(0xFFFFFFFFu, p, 16);
            p += __shfl_xor_sync(0xFFFFFFFFu, p, 8);
            p += __shfl_xor_sync(0xFFFFFFFFu, p, 4);
            p += __shfl_xor_sync(0xFFFFFFFFu, p, 2);
            p += __shfl_xor_sync(0xFFFFFFFFu, p, 1);
            if (lane == 0) s.pred[b * 2 + o] = p + s.bl[o];
        }
        __syncthreads();
        if (tid < 8) {
            int b = tid >> 1, o = tid & 1;
            int gb = gb0 + b;
            float base = (w < 4) ? traj[(gb * TT + 3 + w) * 3 + 1 + o]
                                 : s.winbuf[(b * 4 + 3) * 2 + o];
            float pn = base + s.pred[b * 2 + o];
            float t1 = s.winbuf[(b * 4 + 1) * 2 + o];
            float t2 = s.winbuf[(b * 4 + 2) * 2 + o];
            float t3 = s.winbuf[(b * 4 + 3) * 2 + o];
            s.winbuf[(b * 4 + 0) * 2 + o] = t1;
            s.winbuf[(b * 4 + 1) * 2 + o] = t2;
            s.winbuf[(b * 4 + 2) * 2 + o] = t3;
            s.winbuf[(b * 4 + 3) * 2 + o] = pn;
            if (rank == 0) out[(gb * NWIN + w) * 2 + o] = pn;
        }
        __syncthreads();
    }

    // ---- final hidden/cell states from acting-lane registers
    if (kq == 0) {
        int jg = (int)rank * 32 + u;
        const int OFF_H = 128 * NWIN * 2;          // 64512
        const int OFF_C = OFF_H + 2 * 128 * HID;   // 97280
#pragma unroll
        for (int j = 0; j < 2; j++) {
            int gb = gb0 + 2 * gh + j;
            out[OFF_H + 0 * 128 * HID + gb * HID + jg] = h0last[j];
            out[OFF_H + 1 * 128 * HID + gb * HID + jg] = h1last[j];
            out[OFF_C + 0 * 128 * HID + gb * HID + jg] = c0[j];
            out[OFF_C + 1 * 128 * HID + gb * HID + jg] = c1[j];
        }
    }
}

extern "C" void kernel_launch(void* const* d_in, const int* in_sizes, int n_in,
                              void* d_out, int out_size) {
    const float* traj = (const float*)d_in[0];
    const float* Wih0 = (const float*)d_in[1];
    const float* Whh0 = (const float*)d_in[2];
    const float* bih0 = (const float*)d_in[3];
    const float* bhh0 = (const float*)d_in[4];
    const float* Wih1 = (const float*)d_in[5];
    const float* Whh1 = (const float*)d_in[6];
    const float* bih1 = (const float*)d_in[7];
    const float* bhh1 = (const float*)d_in[8];
    const float* Wl   = (const float*)d_in[9];
    const float* bl   = (const float*)d_in[10];
    float* out = (float*)d_out;

    int smem = (int)sizeof(Smem);
    cudaFuncSetAttribute(lstm_kernel, cudaFuncAttributeMaxDynamicSharedMemorySize, smem);
    lstm_kernel<<<128, NTHREADS, smem>>>(traj, Wih0, Whh0, bih0, bhh0,
                                         Wih1, Whh1, bih1, bhh1, Wl, bl, out);
}

// round 11
// speedup vs baseline: 2.2950x; 2.2950x over previous
#include <cuda_runtime.h>
#include <cstdint>

typedef unsigned long long ull;

#define NCTA      4
#define HID       128
#define NTHREADS  512
#define NWIN      252
#define TT        256
#define PADW      132     // weight row stride (floats)
#define HB        144     // per-batch h stride: 4 chunks of (32 data + 4 pad)

struct Smem {
    float W1s[128 * PADW];   // Wih1, local row lr = g*32+u  (g=gate, u=unit)
    float U1s[128 * PADW];   // Whh1
    float U0s[128 * PADW];   // Whh0
    float W0s[128 * 4];      // Wih0 (3 cols + pad)
    float b0s[128];
    float b1s[128];
    float h0buf[2][4 * HB];  // ping-pong, cluster-shared, chunk-padded
    float h1buf[2][4 * HB];
    float g1s[4 * 128];      // reduced gates, [b][lr]
    float g0s[4 * 128];
    float xin[4 * 4 * 4];    // [t][b][f pad4]
    float Wl[2 * HID];
    float winbuf[4 * 4 * 2];
    float pred[4 * 2];
    float bl[2];
};

#define FFMA2(acc, w, h) \
    asm("fma.rn.f32x2 %0, %1, %2, %0;" : "+l"(acc) : "l"(w), "l"(h))

__device__ __forceinline__ float hsum2(ull a) {
    float lo, hi;
    asm("mov.b64 {%0, %1}, %2;" : "=f"(lo), "=f"(hi) : "l"(a));
    return lo + hi;
}

__device__ __forceinline__ void cluster_sync_all() {
    asm volatile("barrier.cluster.arrive.aligned;" ::: "memory");
    asm volatile("barrier.cluster.wait.aligned;" ::: "memory");
}

__device__ __forceinline__ float sigf(float x) {
    return 1.0f / (1.0f + __expf(-x));
}

// chunk-padded h index: k -> (k/32)*36 + (k%32)
__device__ __forceinline__ int hIdx(int k) { return (k >> 5) * 36 + (k & 31); }

// broadcast one float to the same smem slot in all 4 cluster CTAs
__device__ __forceinline__ void push4(float v, float* dst) {
    uint32_t la = (uint32_t)__cvta_generic_to_shared(dst);
#pragma unroll
    for (int rr = 0; rr < NCTA; rr++) {
        uint32_t ra;
        asm volatile("mapa.shared::cluster.u32 %0, %1, %2;"
                     : "=r"(ra) : "r"(la), "r"(rr));
        asm volatile("st.shared::cluster.f32 [%0], %1;"
                     :: "r"(ra), "f"(v) : "memory");
    }
}

__device__ __forceinline__ float act2(float g0, float g1, float g2, float g3,
                                      float& c, bool first) {
    float ii = sigf(g0), ff = sigf(g1), tg = tanhf(g2), oo = sigf(g3);
    float cc = first ? ii * tg : fmaf(ff, c, ii * tg);
    c = cc;
    return oo * tanhf(cc);
}

// Pure matvec partials for one row r, k-quarter kq, all 4 batches:
//   g1[b] += Wih1[r]·h0[b] (+ Whh1[r]·h1[b] if HH1)
//   g0[b] += Whh0[r]·h0[b]                    (if G0)
// followed by in-lane-group k reduction and STS of reduced gates.
template<bool HH1, bool G0>
__device__ __forceinline__ void stage_matvec(Smem& s, int pw, int r, int kq,
                                             int lane) {
    const float* w1 = &s.W1s[r * PADW + kq * 32];
    const float* u1 = &s.U1s[r * PADW + kq * 32];
    const float* u0 = &s.U0s[r * PADW + kq * 32];
    const float* h0 = &s.h0buf[pw][kq * 36];
    const float* h1 = &s.h1buf[pw][kq * 36];
    ull A1[4] = {}, A0[4] = {};
#pragma unroll
    for (int k4 = 0; k4 < 8; k4++) {
        ulonglong2 W1v = *(const ulonglong2*)(w1 + 4 * k4);
        ulonglong2 U1v, U0v;
        if (HH1) U1v = *(const ulonglong2*)(u1 + 4 * k4);
        if (G0)  U0v = *(const ulonglong2*)(u0 + 4 * k4);
#pragma unroll
        for (int b = 0; b < 4; b++) {
            ulonglong2 H0 = *(const ulonglong2*)(h0 + b * HB + 4 * k4);
            FFMA2(A1[b], W1v.x, H0.x);
            FFMA2(A1[b], W1v.y, H0.y);
            if (G0) {
                FFMA2(A0[b], U0v.x, H0.x);
                FFMA2(A0[b], U0v.y, H0.y);
            }
            if (HH1) {
                ulonglong2 H1 = *(const ulonglong2*)(h1 + b * HB + 4 * k4);
                FFMA2(A1[b], U1v.x, H1.x);
                FFMA2(A1[b], U1v.y, H1.y);
            }
        }
    }
    float g1v[4], g0v[4];
#pragma unroll
    for (int b = 0; b < 4; b++) {
        g1v[b] = hsum2(A1[b]);
        if (G0) g0v[b] = hsum2(A0[b]);
    }
    // reduce over kq (lane bits 3,4) — butterfly, no barrier
#pragma unroll
    for (int d = 8; d <= 16; d <<= 1) {
#pragma unroll
        for (int b = 0; b < 4; b++) {
            g1v[b] += __shfl_xor_sync(0xFFFFFFFFu, g1v[b], d);
            if (G0) g0v[b] += __shfl_xor_sync(0xFFFFFFFFu, g0v[b], d);
        }
    }
    if (lane < 8) {
#pragma unroll
        for (int b = 0; b < 4; b++) {
            s.g1s[b * 128 + r] = g1v[b];
            if (G0) s.g0s[b * 128 + r] = g0v[b];
        }
    }
}

extern __shared__ float smem_raw[];

__global__ void __cluster_dims__(NCTA, 1, 1) __launch_bounds__(NTHREADS, 1)
lstm_kernel(const float* __restrict__ traj,
            const float* __restrict__ Wih0, const float* __restrict__ Whh0,
            const float* __restrict__ bih0, const float* __restrict__ bhh0,
            const float* __restrict__ Wih1, const float* __restrict__ Whh1,
            const float* __restrict__ bih1, const float* __restrict__ bhh1,
            const float* __restrict__ Wl,   const float* __restrict__ bl,
            float* __restrict__ out) {
    Smem& s = *reinterpret_cast<Smem*>(smem_raw);
    const int tid = threadIdx.x;
    uint32_t rank;
    asm("mov.u32 %0, %%cluster_ctarank;" : "=r"(rank));
    const int cluster = blockIdx.x / NCTA;
    const int gb0 = cluster * 4;

    // ---- weights: local row lr = g*32+u  <->  global row gr = g*128 + rank*32 + u
    for (int i = tid; i < 128 * HID; i += NTHREADS) {
        int lr = i / HID, k = i % HID;
        int g = lr >> 5, u = lr & 31;
        int gr = g * 128 + (int)rank * 32 + u;
        s.W1s[lr * PADW + k] = Wih1[gr * HID + k];
        s.U1s[lr * PADW + k] = Whh1[gr * HID + k];
        s.U0s[lr * PADW + k] = Whh0[gr * HID + k];
    }
    for (int lr = tid; lr < 128; lr += NTHREADS) {
        int g = lr >> 5, u = lr & 31;
        int gr = g * 128 + (int)rank * 32 + u;
        s.W0s[lr * 4 + 0] = Wih0[gr * 3 + 0];
        s.W0s[lr * 4 + 1] = Wih0[gr * 3 + 1];
        s.W0s[lr * 4 + 2] = Wih0[gr * 3 + 2];
        s.W0s[lr * 4 + 3] = 0.0f;
        s.b0s[lr] = bih0[gr] + bhh0[gr];
        s.b1s[lr] = bih1[gr] + bhh1[gr];
    }
    for (int i = tid; i < 2 * HID; i += NTHREADS) s.Wl[i] = Wl[i];
    if (tid < 2) s.bl[tid] = bl[tid];
    __syncthreads();
    cluster_sync_all();

    const int lane = tid & 31;
    const int r    = (tid >> 5) * 8 + (lane & 7);  // gate row 0..127
    const int kq   = lane >> 3;                    // k-quarter 0..3

    // activation-thread identity (tid < 128): batch ab, unit u
    const int ab = tid >> 5;       // 0..3 when tid<128
    const int au = tid & 31;
    const int jg = (int)rank * 32 + au;
    const int hix = hIdx(jg);

    int pw = 0;
    float c0 = 0.f, c1 = 0.f, h0last = 0.f, h1last = 0.f;

    for (int w = 0; w < NWIN; w++) {
        // ---- build window inputs xin[t][b][f]
        if (tid < 64) {
            int t = tid >> 4, b = (tid >> 2) & 3, f = tid & 3;
            if (f < 3) {
                int gb = gb0 + b;
                float v;
                if (w == 0) {
                    v = traj[(gb * TT + t) * 3 + f];
                } else if (w < 4) {
                    if (t < 3) v = traj[(gb * TT + (w + t)) * 3 + f];
                    else v = (f == 0) ? traj[(gb * TT + (4 + w)) * 3 + 0]
                                      : s.winbuf[(b * 4 + 3) * 2 + (f - 1)];
                } else {
                    v = (f < 2) ? s.winbuf[(b * 4 + t) * 2 + f]
                                : traj[(gb * TT + (w + t)) * 3 + 0];
                }
                s.xin[(t * 4 + b) * 4 + f] = v;
            }
        }
        __syncthreads();

        // ---- s0: layer-0 @ t=0 (x only)
        if (tid < 128) {
            const float* x = &s.xin[(0 * 4 + ab) * 4];
            float g4[4];
#pragma unroll
            for (int g = 0; g < 4; g++) {
                int lr = g * 32 + au;
                const float* wv = &s.W0s[lr * 4];
                g4[g] = s.b0s[lr] + wv[0] * x[0] + wv[1] * x[1] + wv[2] * x[2];
            }
            float h0 = act2(g4[0], g4[1], g4[2], g4[3], c0, true);
            h0last = h0;
            push4(h0, &s.h0buf[pw ^ 1][ab * HB + hix]);
        }
        cluster_sync_all();
        pw ^= 1;

        // ---- s1..s3: fused L1[t] + L0[t+1];  s4: L1[3] only
#pragma unroll 1
        for (int st = 0; st < 4; st++) {
            if (st == 0)      stage_matvec<false, true >(s, pw, r, kq, lane);
            else if (st < 3)  stage_matvec<true,  true >(s, pw, r, kq, lane);
            else              stage_matvec<true,  false>(s, pw, r, kq, lane);
            __syncthreads();
            if (tid < 128) {
                float G1[4];
#pragma unroll
                for (int g = 0; g < 4; g++) {
                    int lr = g * 32 + au;
                    G1[g] = s.g1s[ab * 128 + lr] + s.b1s[lr];
                }
                float h1 = act2(G1[0], G1[1], G1[2], G1[3], c1, st == 0);
                h1last = h1;
                push4(h1, &s.h1buf[pw ^ 1][ab * HB + hix]);
                if (st < 3) {
                    const float* x = &s.xin[((st + 1) * 4 + ab) * 4];
                    float G0g[4];
#pragma unroll
                    for (int g = 0; g < 4; g++) {
                        int lr = g * 32 + au;
                        const float* wv = &s.W0s[lr * 4];
                        G0g[g] = s.g0s[ab * 128 + lr] + s.b0s[lr]
                               + wv[0] * x[0] + wv[1] * x[1] + wv[2] * x[2];
                    }
                    float h0 = act2(G0g[0], G0g[1], G0g[2], G0g[3], c0, false);
                    h0last = h0;
                    push4(h0, &s.h0buf[pw ^ 1][ab * HB + hix]);
                }
            }
            cluster_sync_all();
            pw ^= 1;
        }

        // ---- head: pred[b][o] = Wl[o,:]·h1[b,:] + bl[o]
        if (tid < 256) {
            int wid = tid >> 5;
            int b = wid >> 1, o = wid & 1;
            const float4* wl4 = (const float4*)&s.Wl[o * HID];
            float4 a = wl4[lane];
            const float* hb = &s.h1buf[pw][b * HB + (lane >> 3) * 36 + (lane & 7) * 4];
            float4 hh = *(const float4*)hb;
            float p = a.x * hh.x + a.y * hh.y + a.z * hh.z + a.w * hh.w;
            p += __shfl_xor_sync(0xFFFFFFFFu, p, 16);
            p += __shfl_xor_sync(0xFFFFFFFFu, p, 8);
            p += __shfl_xor_sync(0xFFFFFFFFu, p, 4);
            p += __shfl_xor_sync(0xFFFFFFFFu, p, 2);
            p += __shfl_xor_sync(0xFFFFFFFFu, p, 1);
            if (lane == 0) s.pred[b * 2 + o] = p + s.bl[o];
        }
        __syncthreads();
        if (tid < 8) {
            int b = tid >> 1, o = tid & 1;
            int gb = gb0 + b;
            float base = (w < 4) ? traj[(gb * TT + 3 + w) * 3 + 1 + o]
                                 : s.winbuf[(b * 4 + 3) * 2 + o];
            float pn = base + s.pred[b * 2 + o];
            float t1 = s.winbuf[(b * 4 + 1) * 2 + o];
            float t2 = s.winbuf[(b * 4 + 2) * 2 + o];
            float t3 = s.winbuf[(b * 4 + 3) * 2 + o];
            s.winbuf[(b * 4 + 0) * 2 + o] = t1;
            s.winbuf[(b * 4 + 1) * 2 + o] = t2;
            s.winbuf[(b * 4 + 2) * 2 + o] = t3;
            s.winbuf[(b * 4 + 3) * 2 + o] = pn;
            if (rank == 0) out[(gb * NWIN + w) * 2 + o] = pn;
        }
        __syncthreads();
    }

    // ---- final hidden/cell states from activation-thread registers
    if (tid < 128) {
        int gb = gb0 + ab;
        const int OFF_H = 128 * NWIN * 2;          // 64512
        const int OFF_C = OFF_H + 2 * 128 * HID;   // 97280
        out[OFF_H + 0 * 128 * HID + gb * HID + jg] = h0last;
        out[OFF_H + 1 * 128 * HID + gb * HID + jg] = h1last;
        out[OFF_C + 0 * 128 * HID + gb * HID + jg] = c0;
        out[OFF_C + 1 * 128 * HID + gb * HID + jg] = c1;
    }
}

extern "C" void kernel_launch(void* const* d_in, const int* in_sizes, int n_in,
                              void* d_out, int out_size) {
    const float* traj = (const float*)d_in[0];
    const float* Wih0 = (const float*)d_in[1];
    const float* Whh0 = (const float*)d_in[2];
    const float* bih0 = (const float*)d_in[3];
    const float* bhh0 = (const float*)d_in[4];
    const float* Wih1 = (const float*)d_in[5];
    const float* Whh1 = (const float*)d_in[6];
    const float* bih1 = (const float*)d_in[7];
    const float* bhh1 = (const float*)d_in[8];
    const float* Wl   = (const float*)d_in[9];
    const float* bl   = (const float*)d_in[10];
    float* out = (float*)d_out;

    int smem = (int)sizeof(Smem);
    cudaFuncSetAttribute(lstm_kernel, cudaFuncAttributeMaxDynamicSharedMemorySize, smem);
    lstm_kernel<<<128, NTHREADS, smem>>>(traj, Wih0, Whh0, bih0, bhh0,
                                         Wih1, Whh1, bih1, bhh1, Wl, bl, out);
}

// round 12
// speedup vs baseline: 2.4052x; 1.0480x over previous
#include <cuda_runtime.h>
#include <cstdint>

typedef unsigned long long ull;

#define NCTA      4
#define HID       128
#define NTHREADS  512
#define NWIN      252
#define TT        256
#define PADW      132     // weight row stride (floats)
#define HB        144     // per-batch h stride: 4 chunks of (32 data + 4 pad)

// row layout: lr = w*8 + g*2 + j   (warp w owns units au=2w+j, j in {0,1})
struct Smem {
    float W1s[128 * PADW];   // Wih1
    float U1s[128 * PADW];   // Whh1
    float U0s[128 * PADW];   // Whh0
    float W0s[128 * 4];      // Wih0 (3 cols + pad)
    float b0s[128];
    float b1s[128];
    float h0buf[2][4 * HB];  // ping-pong, cluster-shared, chunk-padded
    float h1buf[2][4 * HB];
    float xin[4 * 4 * 4];    // [t][b][f pad4]
    float Wl[2 * HID];
    float winbuf[4 * 4 * 2];
    float pred[4 * 2];
    float bl[2];
};

#define FFMA2(acc, w, h) \
    asm("fma.rn.f32x2 %0, %1, %2, %0;" : "+l"(acc) : "l"(w), "l"(h))

__device__ __forceinline__ float hsum2(ull a) {
    float lo, hi;
    asm("mov.b64 {%0, %1}, %2;" : "=f"(lo), "=f"(hi) : "l"(a));
    return lo + hi;
}

__device__ __forceinline__ void cluster_sync_all() {
    asm volatile("barrier.cluster.arrive.aligned;" ::: "memory");
    asm volatile("barrier.cluster.wait.aligned;" ::: "memory");
}

__device__ __forceinline__ float sigfast(float x) {
    float e = __expf(-x);
    return __fdividef(1.0f, 1.0f + e);
}
__device__ __forceinline__ float tanhfast(float x) {
    float ax = fabsf(x);
    float e = __expf(-2.0f * ax);
    float t = __fdividef(1.0f - e, 1.0f + e);
    return copysignf(t, x);
}

// chunk-padded h index: k -> (k/32)*36 + (k%32)
__device__ __forceinline__ int hIdx(int k) { return (k >> 5) * 36 + (k & 31); }

// broadcast one float to the same smem slot in all 4 cluster CTAs
__device__ __forceinline__ void push4(float v, float* dst) {
    uint32_t la = (uint32_t)__cvta_generic_to_shared(dst);
#pragma unroll
    for (int rr = 0; rr < NCTA; rr++) {
        uint32_t ra;
        asm volatile("mapa.shared::cluster.u32 %0, %1, %2;"
                     : "=r"(ra) : "r"(la), "r"(rr));
        asm volatile("st.shared::cluster.f32 [%0], %1;"
                     :: "r"(ra), "f"(v) : "memory");
    }
}

__device__ __forceinline__ float act2(float g0, float g1, float g2, float g3,
                                      float& c, bool first) {
    float ii = sigfast(g0), ff = sigfast(g1), tg = tanhfast(g2), oo = sigfast(g3);
    float cc = first ? ii * tg : fmaf(ff, c, ii * tg);
    c = cc;
    return oo * tanhfast(cc);
}

// reduce-scatter over kq (lane bits 3,4): in g[0..3] per-batch partials,
// out: this lane's total for batch b = lane>>3.
__device__ __forceinline__ float rscat4(const float* g, int lane) {
    const bool b4 = (lane & 16) != 0, b3 = (lane & 8) != 0;
    float s0 = b4 ? g[0] : g[2];
    float s1 = b4 ? g[1] : g[3];
    float r0 = __shfl_xor_sync(0xFFFFFFFFu, s0, 16);
    float r1 = __shfl_xor_sync(0xFFFFFFFFu, s1, 16);
    float k0 = (b4 ? g[2] : g[0]) + r0;
    float k1 = (b4 ? g[3] : g[1]) + r1;
    float s2 = b3 ? k0 : k1;
    float r2 = __shfl_xor_sync(0xFFFFFFFFu, s2, 8);
    return (b3 ? k1 : k0) + r2;
}

// One fused stage, fully in-warp after the matvec:
//   gates1 = Wih1·h0 (+ Whh1·h1 if HH1);  gates0 = Whh0·h0 (if G0)
// reduce-scatter + gather via shfl, activation + DSMEM push by acting lanes.
template<bool HH1, bool G0, bool FIRST1>
__device__ __forceinline__ void stage(Smem& s, int pw, int wid, int lane,
                                      int kq, int rl, int t_next,
                                      float& c0, float& c1,
                                      float& h0last, float& h1last, int hix) {
    const int lr = wid * 8 + rl;
    const float* w1 = &s.W1s[lr * PADW + kq * 32];
    const float* u1 = &s.U1s[lr * PADW + kq * 32];
    const float* u0 = &s.U0s[lr * PADW + kq * 32];
    const float* h0 = &s.h0buf[pw][kq * 36];
    const float* h1 = &s.h1buf[pw][kq * 36];
    ull A1[4] = {}, A0[4] = {};
#pragma unroll
    for (int k4 = 0; k4 < 8; k4++) {
        ulonglong2 W1v = *(const ulonglong2*)(w1 + 4 * k4);
        ulonglong2 U1v, U0v;
        if (HH1) U1v = *(const ulonglong2*)(u1 + 4 * k4);
        if (G0)  U0v = *(const ulonglong2*)(u0 + 4 * k4);
#pragma unroll
        for (int b = 0; b < 4; b++) {
            ulonglong2 H0 = *(const ulonglong2*)(h0 + b * HB + 4 * k4);
            FFMA2(A1[b], W1v.x, H0.x);
            FFMA2(A1[b], W1v.y, H0.y);
            if (G0) {
                FFMA2(A0[b], U0v.x, H0.x);
                FFMA2(A0[b], U0v.y, H0.y);
            }
            if (HH1) {
                ulonglong2 H1 = *(const ulonglong2*)(h1 + b * HB + 4 * k4);
                FFMA2(A1[b], U1v.x, H1.x);
                FFMA2(A1[b], U1v.y, H1.y);
            }
        }
    }
    float g1v[4], g0v[4];
#pragma unroll
    for (int b = 0; b < 4; b++) {
        g1v[b] = hsum2(A1[b]);
        if (G0) g0v[b] = hsum2(A0[b]);
    }
    float res1 = rscat4(g1v, lane);
    float res0 = 0.0f;
    if (G0) res0 = rscat4(g0v, lane);
    // gather 4 gates for (unit j=lane&1, batch b=lane>>3) from same-kq lanes
    float G1[4], G0g[4];
#pragma unroll
    for (int g = 0; g < 4; g++) {
        int src = (lane & 24) | (g * 2 + (lane & 1));
        G1[g] = __shfl_sync(0xFFFFFFFFu, res1, src);
        if (G0) G0g[g] = __shfl_sync(0xFFFFFFFFu, res0, src);
    }
    if ((lane & 7) < 2) {
        const int b = lane >> 3, j = lane & 1;
        const int lrb = wid * 8 + j;
        float h1n = act2(G1[0] + s.b1s[lrb + 0], G1[1] + s.b1s[lrb + 2],
                         G1[2] + s.b1s[lrb + 4], G1[3] + s.b1s[lrb + 6],
                         c1, FIRST1);
        h1last = h1n;
        push4(h1n, &s.h1buf[pw ^ 1][b * HB + hix]);
        if (G0) {
            const float* x = &s.xin[(t_next * 4 + b) * 4];
            float gg[4];
#pragma unroll
            for (int g = 0; g < 4; g++) {
                int lr2 = lrb + g * 2;
                const float* wv = &s.W0s[lr2 * 4];
                gg[g] = G0g[g] + s.b0s[lr2]
                      + wv[0] * x[0] + wv[1] * x[1] + wv[2] * x[2];
            }
            float h0n = act2(gg[0], gg[1], gg[2], gg[3], c0, false);
            h0last = h0n;
            push4(h0n, &s.h0buf[pw ^ 1][b * HB + hix]);
        }
    }
}

extern __shared__ float smem_raw[];

__global__ void __cluster_dims__(NCTA, 1, 1) __launch_bounds__(NTHREADS, 1)
lstm_kernel(const float* __restrict__ traj,
            const float* __restrict__ Wih0, const float* __restrict__ Whh0,
            const float* __restrict__ bih0, const float* __restrict__ bhh0,
            const float* __restrict__ Wih1, const float* __restrict__ Whh1,
            const float* __restrict__ bih1, const float* __restrict__ bhh1,
            const float* __restrict__ Wl,   const float* __restrict__ bl,
            float* __restrict__ out) {
    Smem& s = *reinterpret_cast<Smem*>(smem_raw);
    const int tid = threadIdx.x;
    uint32_t rank;
    asm("mov.u32 %0, %%cluster_ctarank;" : "=r"(rank));
    const int cluster = blockIdx.x / NCTA;
    const int gb0 = cluster * 4;

    // ---- weights: local row lr = w*8 + g*2 + j  <->  global gr = g*128 + rank*32 + 2w+j
    for (int i = tid; i < 128 * HID; i += NTHREADS) {
        int lr = i / HID, k = i % HID;
        int wv = lr >> 3, rl = lr & 7, g = rl >> 1, j = rl & 1;
        int gr = g * 128 + (int)rank * 32 + 2 * wv + j;
        s.W1s[lr * PADW + k] = Wih1[gr * HID + k];
        s.U1s[lr * PADW + k] = Whh1[gr * HID + k];
        s.U0s[lr * PADW + k] = Whh0[gr * HID + k];
    }
    for (int lr = tid; lr < 128; lr += NTHREADS) {
        int wv = lr >> 3, rl = lr & 7, g = rl >> 1, j = rl & 1;
        int gr = g * 128 + (int)rank * 32 + 2 * wv + j;
        s.W0s[lr * 4 + 0] = Wih0[gr * 3 + 0];
        s.W0s[lr * 4 + 1] = Wih0[gr * 3 + 1];
        s.W0s[lr * 4 + 2] = Wih0[gr * 3 + 2];
        s.W0s[lr * 4 + 3] = 0.0f;
        s.b0s[lr] = bih0[gr] + bhh0[gr];
        s.b1s[lr] = bih1[gr] + bhh1[gr];
    }
    for (int i = tid; i < 2 * HID; i += NTHREADS) s.Wl[i] = Wl[i];
    if (tid < 2) s.bl[tid] = bl[tid];
    __syncthreads();
    cluster_sync_all();

    const int wid  = tid >> 5;
    const int lane = tid & 31;
    const int kq   = lane >> 3;      // k-quarter
    const int rl   = lane & 7;       // row within warp = g*2+j
    // acting-lane identity (lane&7 < 2): unit au = 2*wid + j, batch b = lane>>3
    const int au  = 2 * wid + (lane & 1);
    const int jg  = (int)rank * 32 + au;
    const int hix = hIdx(jg);

    int pw = 0;
    float c0 = 0.f, c1 = 0.f, h0last = 0.f, h1last = 0.f;

    for (int w = 0; w < NWIN; w++) {
        // ---- build window inputs xin[t][b][f]
        if (tid < 64) {
            int t = tid >> 4, b = (tid >> 2) & 3, f = tid & 3;
            if (f < 3) {
                int gb = gb0 + b;
                float v;
                if (w == 0) {
                    v = traj[(gb * TT + t) * 3 + f];
                } else if (w < 4) {
                    if (t < 3) v = traj[(gb * TT + (w + t)) * 3 + f];
                    else v = (f == 0) ? traj[(gb * TT + (4 + w)) * 3 + 0]
                                      : s.winbuf[(b * 4 + 3) * 2 + (f - 1)];
                } else {
                    v = (f < 2) ? s.winbuf[(b * 4 + t) * 2 + f]
                                : traj[(gb * TT + (w + t)) * 3 + 0];
                }
                s.xin[(t * 4 + b) * 4 + f] = v;
            }
        }
        __syncthreads();

        // ---- s0: layer-0 @ t=0 (x only), acting lanes of every warp
        if ((lane & 7) < 2) {
            int b = lane >> 3, j = lane & 1;
            const float* x = &s.xin[(0 * 4 + b) * 4];
            float g4[4];
#pragma unroll
            for (int g = 0; g < 4; g++) {
                int lr = wid * 8 + g * 2 + j;
                const float* wv = &s.W0s[lr * 4];
                g4[g] = s.b0s[lr] + wv[0] * x[0] + wv[1] * x[1] + wv[2] * x[2];
            }
            float h0n = act2(g4[0], g4[1], g4[2], g4[3], c0, true);
            h0last = h0n;
            push4(h0n, &s.h0buf[pw ^ 1][b * HB + hix]);
        }
        cluster_sync_all();
        pw ^= 1;

        // ---- s1..s3: fused L1[t] + L0[t+1];  s4: L1[3] only — one barrier each
        stage<false, true, true >(s, pw, wid, lane, kq, rl, 1, c0, c1, h0last, h1last, hix);
        cluster_sync_all(); pw ^= 1;
        stage<true,  true, false>(s, pw, wid, lane, kq, rl, 2, c0, c1, h0last, h1last, hix);
        cluster_sync_all(); pw ^= 1;
        stage<true,  true, false>(s, pw, wid, lane, kq, rl, 3, c0, c1, h0last, h1last, hix);
        cluster_sync_all(); pw ^= 1;
        stage<true,  false, false>(s, pw, wid, lane, kq, rl, 0, c0, c1, h0last, h1last, hix);
        cluster_sync_all(); pw ^= 1;

        // ---- head: pred[b][o] = Wl[o,:]·h1[b,:] + bl[o]
        if (tid < 256) {
            int hw = tid >> 5;
            int b = hw >> 1, o = hw & 1;
            const float4* wl4 = (const float4*)&s.Wl[o * HID];
            float4 a = wl4[lane];
            const float* hb = &s.h1buf[pw][b * HB + (lane >> 3) * 36 + (lane & 7) * 4];
            float4 hh = *(const float4*)hb;
            float p = a.x * hh.x + a.y * hh.y + a.z * hh.z + a.w * hh.w;
            p += __shfl_xor_sync(0xFFFFFFFFu, p, 16);
            p += __shfl_xor_sync(0xFFFFFFFFu, p, 8);
            p += __shfl_xor_sync(0xFFFFFFFFu, p, 4);
            p += __shfl_xor_sync(0xFFFFFFFFu, p, 2);
            p += __shfl_xor_sync(0xFFFFFFFFu, p, 1);
            if (lane == 0) s.pred[b * 2 + o] = p + s.bl[o];
        }
        __syncthreads();
        if (tid < 8) {
            int b = tid >> 1, o = tid & 1;
            int gb = gb0 + b;
            float base = (w < 4) ? traj[(gb * TT + 3 + w) * 3 + 1 + o]
                                 : s.winbuf[(b * 4 + 3) * 2 + o];
            float pn = base + s.pred[b * 2 + o];
            float t1 = s.winbuf[(b * 4 + 1) * 2 + o];
            float t2 = s.winbuf[(b * 4 + 2) * 2 + o];
            float t3 = s.winbuf[(b * 4 + 3) * 2 + o];
            s.winbuf[(b * 4 + 0) * 2 + o] = t1;
            s.winbuf[(b * 4 + 1) * 2 + o] = t2;
            s.winbuf[(b * 4 + 2) * 2 + o] = t3;
            s.winbuf[(b * 4 + 3) * 2 + o] = pn;
            if (rank == 0) out[(gb * NWIN + w) * 2 + o] = pn;
        }
        __syncthreads();
    }

    // ---- final hidden/cell states from acting-lane registers
    if ((lane & 7) < 2) {
        int b = lane >> 3;
        int gb = gb0 + b;
        const int OFF_H = 128 * NWIN * 2;          // 64512
        const int OFF_C = OFF_H + 2 * 128 * HID;   // 97280
        out[OFF_H + 0 * 128 * HID + gb * HID + jg] = h0last;
        out[OFF_H + 1 * 128 * HID + gb * HID + jg] = h1last;
        out[OFF_C + 0 * 128 * HID + gb * HID + jg] = c0;
        out[OFF_C + 1 * 128 * HID + gb * HID + jg] = c1;
    }
}

extern "C" void kernel_launch(void* const* d_in, const int* in_sizes, int n_in,
                              void* d_out, int out_size) {
    const float* traj = (const float*)d_in[0];
    const float* Wih0 = (const float*)d_in[1];
    const float* Whh0 = (const float*)d_in[2];
    const float* bih0 = (const float*)d_in[3];
    const float* bhh0 = (const float*)d_in[4];
    const float* Wih1 = (const float*)d_in[5];
    const float* Whh1 = (const float*)d_in[6];
    const float* bih1 = (const float*)d_in[7];
    const float* bhh1 = (const float*)d_in[8];
    const float* Wl   = (const float*)d_in[9];
    const float* bl   = (const float*)d_in[10];
    float* out = (float*)d_out;

    int smem = (int)sizeof(Smem);
    cudaFuncSetAttribute(lstm_kernel, cudaFuncAttributeMaxDynamicSharedMemorySize, smem);
    lstm_kernel<<<128, NTHREADS, smem>>>(traj, Wih0, Whh0, bih0, bhh0,
                                         Wih1, Whh1, bih1, bhh1, Wl, bl, out);
}